// round 4
// baseline (speedup 1.0000x reference)
#include <cuda_runtime.h>
#include <cuda_fp16.h>

#define NN 100000
#define EE 1600000
#define NB 98   /* ceil(NN/1024) */

typedef unsigned long long u64;

// ---------------- device scratch ----------------
__device__ int    d_counts[NN];
__device__ int    d_offs[NN];
__device__ int    d_cursor[NN];
__device__ int    d_bsums[NB];
__device__ int    d_srcs[EE];
__device__ float  d_dinv[NN];
__device__ __half d_g0h[NN * 32];   // half(dinv * x)
__device__ __half d_a0h[NN * 32];   // half(layer-1 aggregated input)
__device__ __half d_g2h[NN * 32];   // half(dinv * mlp(a0))

// ---------------- f32x2 helpers ----------------
__device__ __forceinline__ u64 pack2(float lo, float hi) {
    u64 r; asm("mov.b64 %0, {%1, %2};" : "=l"(r) : "f"(lo), "f"(hi)); return r;
}
__device__ __forceinline__ u64 fma2(u64 a, u64 b, u64 c) {
    u64 d; asm("fma.rn.f32x2 %0, %1, %2, %3;" : "=l"(d) : "l"(a), "l"(b), "l"(c)); return d;
}
__device__ __forceinline__ float2 unpack2(u64 v) {
    float2 f; asm("mov.b64 {%0, %1}, %2;" : "=f"(f.x), "=f"(f.y) : "l"(v)); return f;
}

// ---------------- CSR build ----------------
__global__ void zero_counts_kernel() {
    int i = blockIdx.x * blockDim.x + threadIdx.x;
    if (i < NN) d_counts[i] = 0;
}

__global__ void hist_kernel(const int* __restrict__ ei) {
    int t = blockIdx.x * blockDim.x + threadIdx.x;
    if (t >= EE / 4) return;
    int4 d = reinterpret_cast<const int4*>(ei + EE)[t];
    atomicAdd(&d_counts[d.x], 1);
    atomicAdd(&d_counts[d.y], 1);
    atomicAdd(&d_counts[d.z], 1);
    atomicAdd(&d_counts[d.w], 1);
}

// 256 threads x 4 elems = 1024 per block, warp-shuffle scan
__global__ __launch_bounds__(256) void scan1_kernel() {
    __shared__ int wsums[8];
    int t = threadIdx.x, b = blockIdx.x;
    int lane = t & 31, warp = t >> 5;
    int base = b * 1024 + t * 4;
    int4 c = make_int4(0, 0, 0, 0);
    if (base + 3 < NN) c = *reinterpret_cast<const int4*>(&d_counts[base]);
    else {
        if (base     < NN) c.x = d_counts[base];
        if (base + 1 < NN) c.y = d_counts[base + 1];
        if (base + 2 < NN) c.z = d_counts[base + 2];
        if (base + 3 < NN) c.w = d_counts[base + 3];
    }
    int s = c.x + c.y + c.z + c.w;
    int incl = s;
    #pragma unroll
    for (int o = 1; o < 32; o <<= 1) {
        int v = __shfl_up_sync(0xffffffffu, incl, o);
        if (lane >= o) incl += v;
    }
    if (lane == 31) wsums[warp] = incl;
    __syncthreads();
    if (t < 8) {
        int v = wsums[t];
        int p = v;
        #pragma unroll
        for (int o = 1; o < 8; o <<= 1) {
            int u = __shfl_up_sync(0xffu, p, o);
            if (t >= o) p += u;
        }
        wsums[t] = p - v;
        if (t == 7) d_bsums[b] = p;
    }
    __syncthreads();
    int excl = incl - s + wsums[warp];
    int p0 = excl, p1 = p0 + c.x, p2 = p1 + c.y, p3 = p2 + c.z;
    if (base + 3 < NN) {
        *reinterpret_cast<int4*>(&d_offs[base]) = make_int4(p0, p1, p2, p3);
    } else {
        if (base     < NN) d_offs[base]     = p0;
        if (base + 1 < NN) d_offs[base + 1] = p1;
        if (base + 2 < NN) d_offs[base + 2] = p2;
        if (base + 3 < NN) d_offs[base + 3] = p3;
    }
}

// scan3 + prep fused: cross-block base, cursor init, dinv, g0h = half(dinv*x)
__global__ __launch_bounds__(1024) void scan3_prep_kernel(const float* __restrict__ x) {
    __shared__ int wsum[32];
    __shared__ int base_sh;
    int t = threadIdx.x, b = blockIdx.x;
    int v = (t < b) ? d_bsums[t] : 0;
    #pragma unroll
    for (int o = 16; o > 0; o >>= 1) v += __shfl_down_sync(0xffffffffu, v, o);
    if ((t & 31) == 0) wsum[t >> 5] = v;
    __syncthreads();
    if (t < 32) {
        int w = wsum[t];
        #pragma unroll
        for (int o = 16; o > 0; o >>= 1) w += __shfl_down_sync(0xffffffffu, w, o);
        if (t == 0) base_sh = w;
    }
    __syncthreads();
    int idx = b * 1024 + t;
    if (idx < NN) {
        int o = d_offs[idx] + base_sh;
        d_offs[idx] = o;
        d_cursor[idx] = o;
    }
    // prep for this block's 1024 nodes: 8192 float4 chunks, linear for coalescing
    int gbase = b * 8192;
    #pragma unroll
    for (int q = 0; q < 8; q++) {
        int u = gbase + q * 1024 + t;
        if (u < NN * 8) {
            int node = u >> 3;
            float dv = rsqrtf((float)(d_counts[node] + 1));
            if ((u & 7) == 0) d_dinv[node] = dv;
            float4 vv = reinterpret_cast<const float4*>(x)[u];
            __half2 h01 = __floats2half2_rn(vv.x * dv, vv.y * dv);
            __half2 h23 = __floats2half2_rn(vv.z * dv, vv.w * dv);
            uint2 uu;
            uu.x = *reinterpret_cast<unsigned*>(&h01);
            uu.y = *reinterpret_cast<unsigned*>(&h23);
            reinterpret_cast<uint2*>(d_g0h)[u] = uu;
        }
    }
}

__global__ void fill_kernel(const int* __restrict__ ei) {
    int t = blockIdx.x * blockDim.x + threadIdx.x;
    if (t >= EE / 4) return;
    int4 s = reinterpret_cast<const int4*>(ei)[t];
    int4 d = reinterpret_cast<const int4*>(ei + EE)[t];
    d_srcs[atomicAdd(&d_cursor[d.x], 1)] = s.x;
    d_srcs[atomicAdd(&d_cursor[d.y], 1)] = s.y;
    d_srcs[atomicAdd(&d_cursor[d.z], 1)] = s.z;
    d_srcs[atomicAdd(&d_cursor[d.w], 1)] = s.w;
}

// ---------------- aggregation core ----------------
// Warp handles node i; lane = 16*h + f. Half-warp h processes edge (2j+h);
// lane loads half2 of features {2f, 2f+1}. fp32 dual accumulators.
__device__ __forceinline__ float2 agg_node(const __half* __restrict__ g, int i, int f, int h) {
    float2 acc = make_float2(0.f, 0.f);
    float2 accb = make_float2(0.f, 0.f);
    if (h == 0) {   // self-loop term
        unsigned v = *reinterpret_cast<const unsigned*>(g + i * 32 + 2 * f);
        float2 fv = __half22float2(*reinterpret_cast<__half2*>(&v));
        acc.x += fv.x; acc.y += fv.y;
    }
    int lane = threadIdx.x & 31;
    int start = d_offs[i], cnt = d_counts[i];
    int base = 0;
    for (; base + 32 <= cnt; base += 32) {
        int s = d_srcs[start + base + lane];
        #pragma unroll
        for (int j = 0; j < 16; j++) {
            int sj = __shfl_sync(0xffffffffu, s, (j << 1) | h);
            unsigned v = *reinterpret_cast<const unsigned*>(g + sj * 32 + 2 * f);
            float2 fv = __half22float2(*reinterpret_cast<__half2*>(&v));
            if (j & 1) { accb.x += fv.x; accb.y += fv.y; }
            else       { acc.x  += fv.x; acc.y  += fv.y; }
        }
    }
    int rem = cnt - base;
    if (rem > 0) {
        int s = (lane < rem) ? d_srcs[start + base + lane] : 0;
        int pairs = rem >> 1;
        for (int j = 0; j < pairs; j++) {
            int sj = __shfl_sync(0xffffffffu, s, (j << 1) | h);
            unsigned v = *reinterpret_cast<const unsigned*>(g + sj * 32 + 2 * f);
            float2 fv = __half22float2(*reinterpret_cast<__half2*>(&v));
            if (j & 1) { accb.x += fv.x; accb.y += fv.y; }
            else       { acc.x  += fv.x; acc.y  += fv.y; }
        }
        if (rem & 1) {
            int sj = __shfl_sync(0xffffffffu, s, rem - 1);
            if (h == 0) {
                unsigned v = *reinterpret_cast<const unsigned*>(g + sj * 32 + 2 * f);
                float2 fv = __half22float2(*reinterpret_cast<__half2*>(&v));
                acc.x += fv.x; acc.y += fv.y;
            }
        }
    }
    acc.x += accb.x; acc.y += accb.y;
    acc.x += __shfl_down_sync(0xffffffffu, acc.x, 16);
    acc.y += __shfl_down_sync(0xffffffffu, acc.y, 16);
    return acc;
}

__global__ __launch_bounds__(256) void agg0_kernel() {
    int warp = threadIdx.x >> 5, lane = threadIdx.x & 31;
    int i = blockIdx.x * 8 + warp;
    if (i >= NN) return;
    int f = lane & 15, h = lane >> 4;
    float2 acc = agg_node(d_g0h, i, f, h);
    if (h == 0) {
        float dv = d_dinv[i];
        __half2 hh = __floats2half2_rn(acc.x * dv, acc.y * dv);
        reinterpret_cast<unsigned*>(d_a0h)[i * 16 + f] = *reinterpret_cast<unsigned*>(&hh);
    }
}

__global__ __launch_bounds__(256) void agg2_kernel(const float* __restrict__ b2,
                                                   float* __restrict__ out) {
    int warp = threadIdx.x >> 5, lane = threadIdx.x & 31;
    int i = blockIdx.x * 8 + warp;
    if (i >= NN) return;
    int f = lane & 15, h = lane >> 4;
    float2 acc = agg_node(d_g2h, i, f, h);
    if (h == 0) {
        float dv = d_dinv[i];
        float2 o;
        o.x = acc.x * dv + __ldg(&b2[2 * f]);
        o.y = acc.y * dv + __ldg(&b2[2 * f + 1]);
        reinterpret_cast<float2*>(out)[i * 16 + f] = o;
    }
}

// ---------------- fused MLP: g2h = half(dinv * (relu(a0@W1+b1) @ W2)) ----------------
__global__ __launch_bounds__(128) void mlp_kernel(const float* __restrict__ W1,
                                                  const float* __restrict__ b1,
                                                  const float* __restrict__ W2) {
    __shared__ float W1s[32 * 64];
    __shared__ float W2s[64 * 32];
    __shared__ float b1s[64];
    for (int t = threadIdx.x; t < 32 * 64; t += 128) W1s[t] = W1[t];
    for (int t = threadIdx.x; t < 64 * 32; t += 128) W2s[t] = W2[t];
    if (threadIdx.x < 64) b1s[threadIdx.x] = b1[threadIdx.x];
    __syncthreads();
    const u64* W1p = reinterpret_cast<const u64*>(W1s);   // [k][32 pairs]
    const u64* W2p = reinterpret_cast<const u64*>(W2s);   // [jj][16 pairs]

    int i = blockIdx.x * 128 + threadIdx.x;
    if (i >= NN) return;

    float a[32];
    #pragma unroll
    for (int q = 0; q < 4; q++) {
        uint4 u = reinterpret_cast<const uint4*>(d_a0h)[i * 4 + q];
        unsigned w[4] = {u.x, u.y, u.z, u.w};
        #pragma unroll
        for (int p = 0; p < 4; p++) {
            float2 fv = __half22float2(*reinterpret_cast<__half2*>(&w[p]));
            a[q * 8 + 2 * p]     = fv.x;
            a[q * 8 + 2 * p + 1] = fv.y;
        }
    }

    // layer 1: h[64] as 32 packed pairs
    u64 h2[32];
    #pragma unroll
    for (int j = 0; j < 32; j++) h2[j] = pack2(b1s[2*j], b1s[2*j+1]);
    #pragma unroll
    for (int k = 0; k < 32; k++) {
        u64 ak = pack2(a[k], a[k]);
        #pragma unroll
        for (int j = 0; j < 32; j++)
            h2[j] = fma2(ak, W1p[k * 32 + j], h2[j]);
    }

    // relu + layer 2: 16 packed pairs
    u64 acc2[16];
    #pragma unroll
    for (int j = 0; j < 16; j++) acc2[j] = pack2(0.f, 0.f);
    #pragma unroll
    for (int jj = 0; jj < 32; jj++) {
        float2 hp = unpack2(h2[jj]);
        float h0 = fmaxf(hp.x, 0.f), h1 = fmaxf(hp.y, 0.f);
        u64 h0d = pack2(h0, h0), h1d = pack2(h1, h1);
        #pragma unroll
        for (int j = 0; j < 16; j++) acc2[j] = fma2(h0d, W2p[(2*jj)   * 16 + j], acc2[j]);
        #pragma unroll
        for (int j = 0; j < 16; j++) acc2[j] = fma2(h1d, W2p[(2*jj+1) * 16 + j], acc2[j]);
    }

    float dv = d_dinv[i];
    unsigned ou[16];
    #pragma unroll
    for (int j = 0; j < 16; j++) {
        float2 v = unpack2(acc2[j]);
        __half2 hh = __floats2half2_rn(v.x * dv, v.y * dv);
        ou[j] = *reinterpret_cast<unsigned*>(&hh);
    }
    uint4* gp = reinterpret_cast<uint4*>(d_g2h) + i * 4;
    #pragma unroll
    for (int q = 0; q < 4; q++)
        gp[q] = make_uint4(ou[4*q], ou[4*q+1], ou[4*q+2], ou[4*q+3]);
}

// ---------------- launch ----------------
extern "C" void kernel_launch(void* const* d_in, const int* in_sizes, int n_in,
                              void* d_out, int out_size) {
    const float* x  = (const float*)d_in[0];
    const int*   ei = (const int*)  d_in[1];
    const float* W1 = (const float*)d_in[2];
    const float* b1 = (const float*)d_in[3];
    const float* W2 = (const float*)d_in[4];
    const float* b2 = (const float*)d_in[5];
    float* out = (float*)d_out;

    zero_counts_kernel<<<(NN + 255) / 256, 256>>>();
    hist_kernel<<<(EE / 4 + 255) / 256, 256>>>(ei);
    scan1_kernel<<<NB, 256>>>();
    scan3_prep_kernel<<<NB, 1024>>>(x);
    fill_kernel<<<(EE / 4 + 255) / 256, 256>>>(ei);

    agg0_kernel<<<(NN + 7) / 8, 256>>>();
    mlp_kernel<<<(NN + 127) / 128, 128>>>(W1, b1, W2);
    agg2_kernel<<<(NN + 7) / 8, 256>>>(b2, out);
}

// round 5
// speedup vs baseline: 1.0336x; 1.0336x over previous
#include <cuda_runtime.h>
#include <cuda_fp16.h>

#define NN 100000
#define EE 1600000
#define NB 98   /* ceil(NN/1024) */

typedef unsigned long long u64;

// ---------------- device scratch ----------------
__device__ int    d_counts[NN];
__device__ int    d_offs[NN];
__device__ int    d_cursor[NN];
__device__ int    d_bsums[NB];
__device__ int    d_srcs[EE];
__device__ float  d_dinv[NN];
__device__ __half d_g0h[NN * 32];   // half(dinv * x)
__device__ __half d_a0h[NN * 32];   // half(layer-1 aggregated input)
__device__ __half d_g2h[NN * 32];   // half(dinv * mlp(a0))

// ---------------- f32x2 helpers ----------------
__device__ __forceinline__ u64 pack2(float lo, float hi) {
    u64 r; asm("mov.b64 %0, {%1, %2};" : "=l"(r) : "f"(lo), "f"(hi)); return r;
}
__device__ __forceinline__ u64 fma2(u64 a, u64 b, u64 c) {
    u64 d; asm("fma.rn.f32x2 %0, %1, %2, %3;" : "=l"(d) : "l"(a), "l"(b), "l"(c)); return d;
}
__device__ __forceinline__ float2 unpack2(u64 v) {
    float2 f; asm("mov.b64 {%0, %1}, %2;" : "=f"(f.x), "=f"(f.y) : "l"(v)); return f;
}

// ---------------- CSR build ----------------
__global__ void hist_kernel(const int* __restrict__ ei) {
    int t = blockIdx.x * blockDim.x + threadIdx.x;
    if (t >= EE / 4) return;
    int4 d = reinterpret_cast<const int4*>(ei + EE)[t];
    atomicAdd(&d_counts[d.x], 1);
    atomicAdd(&d_counts[d.y], 1);
    atomicAdd(&d_counts[d.z], 1);
    atomicAdd(&d_counts[d.w], 1);
}

// 256 threads x 4 elems = 1024 per block, warp-shuffle scan
__global__ __launch_bounds__(256) void scan1_kernel() {
    __shared__ int wsums[8];
    int t = threadIdx.x, b = blockIdx.x;
    int lane = t & 31, warp = t >> 5;
    int base = b * 1024 + t * 4;
    int4 c = make_int4(0, 0, 0, 0);
    if (base + 3 < NN) c = *reinterpret_cast<const int4*>(&d_counts[base]);
    else {
        if (base     < NN) c.x = d_counts[base];
        if (base + 1 < NN) c.y = d_counts[base + 1];
        if (base + 2 < NN) c.z = d_counts[base + 2];
        if (base + 3 < NN) c.w = d_counts[base + 3];
    }
    int s = c.x + c.y + c.z + c.w;
    int incl = s;
    #pragma unroll
    for (int o = 1; o < 32; o <<= 1) {
        int v = __shfl_up_sync(0xffffffffu, incl, o);
        if (lane >= o) incl += v;
    }
    if (lane == 31) wsums[warp] = incl;
    __syncthreads();
    if (t < 8) {
        int v = wsums[t];
        int p = v;
        #pragma unroll
        for (int o = 1; o < 8; o <<= 1) {
            int u = __shfl_up_sync(0xffu, p, o);
            if (t >= o) p += u;
        }
        wsums[t] = p - v;
        if (t == 7) d_bsums[b] = p;
    }
    __syncthreads();
    int excl = incl - s + wsums[warp];
    int p0 = excl, p1 = p0 + c.x, p2 = p1 + c.y, p3 = p2 + c.z;
    if (base + 3 < NN) {
        *reinterpret_cast<int4*>(&d_offs[base]) = make_int4(p0, p1, p2, p3);
    } else {
        if (base     < NN) d_offs[base]     = p0;
        if (base + 1 < NN) d_offs[base + 1] = p1;
        if (base + 2 < NN) d_offs[base + 2] = p2;
        if (base + 3 < NN) d_offs[base + 3] = p3;
    }
}

// cross-block base + cursor init
__global__ void scan3_kernel() {
    __shared__ int wsum[32];
    __shared__ int base_sh;
    int t = threadIdx.x, b = blockIdx.x;
    int v = (t < b) ? d_bsums[t] : 0;
    #pragma unroll
    for (int o = 16; o > 0; o >>= 1) v += __shfl_down_sync(0xffffffffu, v, o);
    if ((t & 31) == 0) wsum[t >> 5] = v;
    __syncthreads();
    if (t < 32) {
        int w = wsum[t];
        #pragma unroll
        for (int o = 16; o > 0; o >>= 1) w += __shfl_down_sync(0xffffffffu, w, o);
        if (t == 0) base_sh = w;
    }
    __syncthreads();
    int idx = b * 1024 + t;
    if (idx < NN) {
        int o = d_offs[idx] + base_sh;
        d_offs[idx] = o;
        d_cursor[idx] = o;
    }
}

__global__ void fill_kernel(const int* __restrict__ ei) {
    int t = blockIdx.x * blockDim.x + threadIdx.x;
    if (t >= EE / 4) return;
    int4 s = reinterpret_cast<const int4*>(ei)[t];
    int4 d = reinterpret_cast<const int4*>(ei + EE)[t];
    d_srcs[atomicAdd(&d_cursor[d.x], 1)] = s.x;
    d_srcs[atomicAdd(&d_cursor[d.y], 1)] = s.y;
    d_srcs[atomicAdd(&d_cursor[d.z], 1)] = s.z;
    d_srcs[atomicAdd(&d_cursor[d.w], 1)] = s.w;
}

// ---------------- prep: dinv = rsqrt(deg), g0h = half(dinv * x) ----------------
__global__ void prep_kernel(const float* __restrict__ x) {
    int t = blockIdx.x * blockDim.x + threadIdx.x;
    if (t >= NN * 8) return;
    int i = t >> 3;
    float dv = rsqrtf((float)(d_counts[i] + 1));
    if ((t & 7) == 0) d_dinv[i] = dv;
    float4 v = reinterpret_cast<const float4*>(x)[t];
    __half2 h01 = __floats2half2_rn(v.x * dv, v.y * dv);
    __half2 h23 = __floats2half2_rn(v.z * dv, v.w * dv);
    uint2 u;
    u.x = *reinterpret_cast<unsigned*>(&h01);
    u.y = *reinterpret_cast<unsigned*>(&h23);
    reinterpret_cast<uint2*>(d_g0h)[t] = u;
}

// ---------------- 32-dim aggregation, lane = feature ----------------
// Predicated fully-unrolled first 32 edges (covers ~all nodes for Poisson(16)),
// 8-step uniform-branch blocks for MLP; rare dynamic fallback for cnt > 32.
__device__ __forceinline__ float agg32h(const __half* __restrict__ g, int i, int lane) {
    float acc = __half2float(__ldg(&g[i * 32 + lane]));   // self loop
    float accb = 0.f;
    int start = d_offs[i], cnt = d_counts[i];
    int s = (lane < cnt) ? __ldg(&d_srcs[start + lane]) : 0;
    int m = cnt < 32 ? cnt : 32;
    #pragma unroll
    for (int j0 = 0; j0 < 32; j0 += 8) {
        if (j0 < m) {   // warp-uniform: skip empty blocks
            #pragma unroll
            for (int jj = 0; jj < 8; jj++) {
                int j = j0 + jj;
                int sj = __shfl_sync(0xffffffffu, s, j);
                float v = (j < m) ? __half2float(__ldg(&g[sj * 32 + lane])) : 0.f;
                if (jj & 1) accb += v; else acc += v;
            }
        }
    }
    // overflow (rare): cnt > 32
    for (int base = 32; base < cnt; base += 32) {
        int rem = cnt - base;
        int sm = (lane < rem) ? __ldg(&d_srcs[start + base + lane]) : 0;
        int mm = rem < 32 ? rem : 32;
        for (int j = 0; j < mm; j++) {
            int sj = __shfl_sync(0xffffffffu, sm, j);
            acc += __half2float(__ldg(&g[sj * 32 + lane]));
        }
    }
    return acc + accb;
}

__global__ __launch_bounds__(256) void agg0_kernel() {
    int warp = threadIdx.x >> 5, lane = threadIdx.x & 31;
    int i = blockIdx.x * 8 + warp;
    if (i >= NN) return;
    float acc = agg32h(d_g0h, i, lane);
    d_a0h[i * 32 + lane] = __float2half_rn(acc * d_dinv[i]);
}

__global__ __launch_bounds__(256) void agg2_kernel(const float* __restrict__ b2,
                                                   float* __restrict__ out) {
    int warp = threadIdx.x >> 5, lane = threadIdx.x & 31;
    int i = blockIdx.x * 8 + warp;
    if (i >= NN) return;
    float acc = agg32h(d_g2h, i, lane);
    out[i * 32 + lane] = acc * d_dinv[i] + __ldg(&b2[lane]);
}

// ---------------- fused MLP: g2h = half(dinv * (relu(a0@W1+b1) @ W2)) ----------------
__global__ __launch_bounds__(128) void mlp_kernel(const float* __restrict__ W1,
                                                  const float* __restrict__ b1,
                                                  const float* __restrict__ W2) {
    __shared__ float W1s[32 * 64];
    __shared__ float W2s[64 * 32];
    __shared__ float b1s[64];
    for (int t = threadIdx.x; t < 32 * 64; t += 128) W1s[t] = W1[t];
    for (int t = threadIdx.x; t < 64 * 32; t += 128) W2s[t] = W2[t];
    if (threadIdx.x < 64) b1s[threadIdx.x] = b1[threadIdx.x];
    __syncthreads();
    const u64* W1p = reinterpret_cast<const u64*>(W1s);   // [k][32 pairs]
    const u64* W2p = reinterpret_cast<const u64*>(W2s);   // [jj][16 pairs]

    int i = blockIdx.x * 128 + threadIdx.x;
    if (i >= NN) return;

    float a[32];
    #pragma unroll
    for (int q = 0; q < 4; q++) {
        uint4 u = reinterpret_cast<const uint4*>(d_a0h)[i * 4 + q];
        unsigned w[4] = {u.x, u.y, u.z, u.w};
        #pragma unroll
        for (int p = 0; p < 4; p++) {
            float2 fv = __half22float2(*reinterpret_cast<__half2*>(&w[p]));
            a[q * 8 + 2 * p]     = fv.x;
            a[q * 8 + 2 * p + 1] = fv.y;
        }
    }

    u64 h2[32];
    #pragma unroll
    for (int j = 0; j < 32; j++) h2[j] = pack2(b1s[2*j], b1s[2*j+1]);
    #pragma unroll
    for (int k = 0; k < 32; k++) {
        u64 ak = pack2(a[k], a[k]);
        #pragma unroll
        for (int j = 0; j < 32; j++)
            h2[j] = fma2(ak, W1p[k * 32 + j], h2[j]);
    }

    u64 acc2[16];
    #pragma unroll
    for (int j = 0; j < 16; j++) acc2[j] = pack2(0.f, 0.f);
    #pragma unroll
    for (int jj = 0; jj < 32; jj++) {
        float2 hp = unpack2(h2[jj]);
        float h0 = fmaxf(hp.x, 0.f), h1 = fmaxf(hp.y, 0.f);
        u64 h0d = pack2(h0, h0), h1d = pack2(h1, h1);
        #pragma unroll
        for (int j = 0; j < 16; j++) acc2[j] = fma2(h0d, W2p[(2*jj)   * 16 + j], acc2[j]);
        #pragma unroll
        for (int j = 0; j < 16; j++) acc2[j] = fma2(h1d, W2p[(2*jj+1) * 16 + j], acc2[j]);
    }

    float dv = d_dinv[i];
    unsigned ou[16];
    #pragma unroll
    for (int j = 0; j < 16; j++) {
        float2 v = unpack2(acc2[j]);
        __half2 hh = __floats2half2_rn(v.x * dv, v.y * dv);
        ou[j] = *reinterpret_cast<unsigned*>(&hh);
    }
    uint4* gp = reinterpret_cast<uint4*>(d_g2h) + i * 4;
    #pragma unroll
    for (int q = 0; q < 4; q++)
        gp[q] = make_uint4(ou[4*q], ou[4*q+1], ou[4*q+2], ou[4*q+3]);
}

// ---------------- launch ----------------
extern "C" void kernel_launch(void* const* d_in, const int* in_sizes, int n_in,
                              void* d_out, int out_size) {
    const float* x  = (const float*)d_in[0];
    const int*   ei = (const int*)  d_in[1];
    const float* W1 = (const float*)d_in[2];
    const float* b1 = (const float*)d_in[3];
    const float* W2 = (const float*)d_in[4];
    const float* b2 = (const float*)d_in[5];
    float* out = (float*)d_out;

    void* counts_ptr = nullptr;
    cudaGetSymbolAddress(&counts_ptr, d_counts);
    cudaMemsetAsync(counts_ptr, 0, NN * sizeof(int));

    hist_kernel<<<(EE / 4 + 255) / 256, 256>>>(ei);          // launch 1
    scan1_kernel<<<NB, 256>>>();                             // launch 2
    scan3_kernel<<<NB, 1024>>>();                            // launch 3
    fill_kernel<<<(EE / 4 + 255) / 256, 256>>>(ei);          // launch 4 (profiled)
    prep_kernel<<<(NN * 8 + 255) / 256, 256>>>(x);           // launch 5

    agg0_kernel<<<(NN + 7) / 8, 256>>>();
    mlp_kernel<<<(NN + 127) / 128, 128>>>(W1, b1, W2);
    agg2_kernel<<<(NN + 7) / 8, 256>>>(b2, out);
}